// round 1
// baseline (speedup 1.0000x reference)
#include <cuda_runtime.h>
#include <math.h>

#define NN      16384
#define IN_DIM  5000
#define HID     64
#define NCLS    4
#define NLEV    11
#define HS_SPLIT 32
#define KT      64

// ---------------- scratch (device globals; no allocation) ----------------
__device__ float g_h[NN * HID];                       // 4 MB, current hidden state (by node id)
__device__ float g_xhat[NN * HID];                    // 4 MB
__device__ float g_xr[NN * HID];
__device__ float g_xz[NN * HID];
__device__ float g_xh[NN * HID];
__device__ float g_hsp[(size_t)HS_SPLIT * NN * HID];  // 128 MB, k-split partial hs (by compact t)
__device__ int   g_order[NN];                         // nodes sorted by level desc
__device__ int   g_segbase[NLEV];
__device__ int   g_cnt[NLEV];

// packed f32x2 FMA (FFMA2): 2 FMA per fma-pipe slot on sm_103a
__device__ __forceinline__ void ffma2(float2 &c, float2 a, float2 b) {
    asm("fma.rn.f32x2 %0, %1, %2, %0;"
        : "+l"(*reinterpret_cast<unsigned long long *>(&c))
        : "l"(*reinterpret_cast<unsigned long long *>(&a)),
          "l"(*reinterpret_cast<unsigned long long *>(&b)));
}

// ---------------- zero hidden state ----------------
__global__ void k_zero() {
    size_t i = (size_t)blockIdx.x * blockDim.x + threadIdx.x;
    *(float4 *)(g_h + 4 * i) = make_float4(0.f, 0.f, 0.f, 0.f);
}

// ---------------- bucket nodes by level (descending segments) ----------------
__global__ void k_order(const int *__restrict__ level) {
    __shared__ int cnt[NLEV];
    __shared__ int off[NLEV];
    int tid = threadIdx.x;
    if (tid < NLEV) cnt[tid] = 0;
    __syncthreads();
    for (int i = tid; i < NN; i += blockDim.x) atomicAdd(&cnt[level[i]], 1);
    __syncthreads();
    if (tid == 0) {
        int acc = 0;
        for (int j = NLEV - 1; j >= 0; --j) {
            off[j] = acc;
            g_segbase[j] = acc;
            g_cnt[j] = cnt[j];
            acc += cnt[j];
        }
    }
    __syncthreads();
    for (int i = tid; i < NN; i += blockDim.x) {
        int l = level[i];
        int pos = atomicAdd(&off[l], 1);
        g_order[pos] = i;
    }
}

// ---------------- shared FFMA2 GEMM micro-tile ----------------
// 64 rows x 64 cols, thread = (rg = tid>>3 -> 4 rows, lane8 = tid&7 -> 4 col-pairs d2 = lane8+8p)
__device__ __forceinline__ void mm_tile(const float (*As)[KT + 4], const float (*Bs)[HID],
                                        float2 acc[4][4], int rg, int lane8) {
#pragma unroll
    for (int kk = 0; kk < KT; kk += 4) {
        float4 a4[4];
#pragma unroll
        for (int q = 0; q < 4; ++q) a4[q] = *(const float4 *)&As[rg * 4 + q][kk];
#pragma unroll
        for (int i = 0; i < 4; ++i) {
            float2 hv[4];
#pragma unroll
            for (int p = 0; p < 4; ++p) hv[p] = *(const float2 *)&Bs[kk + i][2 * (lane8 + 8 * p)];
#pragma unroll
            for (int q = 0; q < 4; ++q) {
                float av = (i == 0) ? a4[q].x : ((i == 1) ? a4[q].y : ((i == 2) ? a4[q].z : a4[q].w));
                float2 aa = make_float2(av, av);
#pragma unroll
                for (int p = 0; p < 4; ++p) ffma2(acc[q][p], aa, hv[p]);
            }
        }
    }
}

// ---------------- embedding GEMM: x_hat = tfidf @ E  (16384x5000 @ 5000x64) ----------------
__global__ __launch_bounds__(128) void k_emb(const float *__restrict__ A, const float *__restrict__ E) {
    __shared__ float As[64][KT + 4];
    __shared__ float Bs[KT][HID];
    const int tid = threadIdx.x;
    const int row0 = blockIdx.x * 64;
    const int lane8 = tid & 7;
    const int rg = tid >> 3;
    float2 acc[4][4];
#pragma unroll
    for (int q = 0; q < 4; ++q)
#pragma unroll
        for (int p = 0; p < 4; ++p) acc[q][p] = make_float2(0.f, 0.f);

    for (int k0 = 0; k0 < IN_DIM; k0 += KT) {
#pragma unroll
        for (int v = 0; v < 8; ++v) {
            int pidx = tid + 128 * v;  // 0..1023
            int r = pidx >> 4, kq = pidx & 15;
            int k = k0 + kq * 4;
            float4 av = (k + 3 < IN_DIM)
                            ? *(const float4 *)(A + (size_t)(row0 + r) * IN_DIM + k)
                            : make_float4(0.f, 0.f, 0.f, 0.f);
            *(float4 *)&As[r][kq * 4] = av;
            int kb = k0 + r;
            float4 bv = (kb < IN_DIM) ? *(const float4 *)(E + (size_t)kb * HID + kq * 4)
                                      : make_float4(0.f, 0.f, 0.f, 0.f);
            *(float4 *)&Bs[r][kq * 4] = bv;
        }
        __syncthreads();
        mm_tile(As, Bs, acc, rg, lane8);
        __syncthreads();
    }
#pragma unroll
    for (int q = 0; q < 4; ++q) {
        size_t r = row0 + rg * 4 + q;
#pragma unroll
        for (int p = 0; p < 4; ++p)
            *(float2 *)(g_xhat + r * HID + 2 * (lane8 + 8 * p)) = acc[q][p];
    }
}

// ---------------- input-side gate projections: xr/xz/xh = x_hat @ W* ----------------
__global__ void k_gates(const float *__restrict__ Wr, const float *__restrict__ Wz,
                        const float *__restrict__ Wh) {
    __shared__ float xs[4][HID];
    const int r = threadIdx.x >> 6;
    const int d = threadIdx.x & 63;
    const size_t row = (size_t)blockIdx.x * 4 + r;
    xs[r][d] = g_xhat[row * HID + d];
    __syncthreads();
    float ar = 0.f, az = 0.f, ah = 0.f;
#pragma unroll
    for (int e = 0; e < HID; ++e) {
        float xe = xs[r][e];
        ar += xe * Wr[e * HID + d];
        az += xe * Wz[e * HID + d];
        ah += xe * Wh[e * HID + d];
    }
    g_xr[row * HID + d] = ar;
    g_xz[row * HID + d] = az;
    g_xh[row * HID + d] = ah;
}

// ---------------- hs partial GEMM for one level: hs[t] = adj[node_t, krange] @ h ----------------
__global__ __launch_bounds__(128) void k_hs(const float *__restrict__ adj, int lev) {
    __shared__ float As[64][KT + 4];
    __shared__ float Hs[KT][HID];
    __shared__ int rowNode[64];
    const int segbase = g_segbase[lev];
    const int cnt = g_cnt[lev];
    const int rb = blockIdx.x * 64;
    if (rb >= cnt) return;
    const int nrows = min(64, cnt - rb);
    const int tid = threadIdx.x;
    if (tid < 64) rowNode[tid] = g_order[segbase + ((tid < nrows) ? rb + tid : rb)];
    __syncthreads();
    const int split = blockIdx.y;
    const int kb = split * (NN / HS_SPLIT);
    const int lane8 = tid & 7;
    const int rg = tid >> 3;
    float2 acc[4][4];
#pragma unroll
    for (int q = 0; q < 4; ++q)
#pragma unroll
        for (int p = 0; p < 4; ++p) acc[q][p] = make_float2(0.f, 0.f);

    for (int k0 = kb; k0 < kb + NN / HS_SPLIT; k0 += KT) {
#pragma unroll
        for (int v = 0; v < 8; ++v) {
            int pidx = tid + 128 * v;
            int r = pidx >> 4, kq = pidx & 15;
            *(float4 *)&As[r][kq * 4] =
                *(const float4 *)(adj + (size_t)rowNode[r] * NN + k0 + kq * 4);
            *(float4 *)&Hs[r][kq * 4] =
                *(const float4 *)(g_h + (size_t)(k0 + r) * HID + kq * 4);
        }
        __syncthreads();
        mm_tile(As, Hs, acc, rg, lane8);
        __syncthreads();
    }
#pragma unroll
    for (int q = 0; q < 4; ++q) {
        int rr = rg * 4 + q;
        if (rr < nrows) {
            size_t t = (size_t)segbase + rb + rr;
#pragma unroll
            for (int p = 0; p < 4; ++p)
                *(float2 *)(g_hsp + ((size_t)split * NN + t) * HID + 2 * (lane8 + 8 * p)) =
                    acc[q][p];
        }
    }
}

// ---------------- GRU cell for one level ----------------
__global__ void k_gru(const float *__restrict__ Ur, const float *__restrict__ Uz,
                      const float *__restrict__ Uh, int lev) {
    __shared__ float hsS[4][HID];
    __shared__ float hrS[4][HID];
    const int segbase = g_segbase[lev];
    const int cnt = g_cnt[lev];
    if (blockIdx.x * 4 >= cnt) return;
    const int r = threadIdx.x >> 6;
    const int d = threadIdx.x & 63;
    const int ridx = blockIdx.x * 4 + r;
    const bool act = ridx < cnt;
    const size_t t = (size_t)segbase + (act ? ridx : (cnt - 1));
    const int node = g_order[t];
    float hsv = 0.f;
#pragma unroll
    for (int s = 0; s < HS_SPLIT; ++s) hsv += g_hsp[((size_t)s * NN + t) * HID + d];
    hsS[r][d] = hsv;
    __syncthreads();
    float rr = g_xr[(size_t)node * HID + d];
    float zz = g_xz[(size_t)node * HID + d];
#pragma unroll
    for (int e = 0; e < HID; ++e) {
        float he = hsS[r][e];
        rr += he * Ur[e * HID + d];
        zz += he * Uz[e * HID + d];
    }
    rr = 1.f / (1.f + expf(-rr));
    zz = 1.f / (1.f + expf(-zz));
    hrS[r][d] = hsv * rr;
    __syncthreads();
    float hh = g_xh[(size_t)node * HID + d];
#pragma unroll
    for (int e = 0; e < HID; ++e) hh += hrS[r][e] * Uh[e * HID + d];
    hh = tanhf(hh);
    if (act) g_h[(size_t)node * HID + d] = (1.f - zz) * hsv + zz * hh;
}

// ---------------- root readout ----------------
__global__ void k_root(const int *__restrict__ level, const float *__restrict__ dec_w,
                       const float *__restrict__ dec_b, float *__restrict__ out) {
    __shared__ float part[4][HID];
    __shared__ float root[HID];
    const int g = threadIdx.x >> 6;
    const int d = threadIdx.x & 63;
    float s = 0.f;
    for (int i = g; i < NN; i += 4)
        if (level[i] == 0) s += g_h[(size_t)i * HID + d];
    part[g][d] = s;
    __syncthreads();
    if (g == 0) root[d] = part[0][d] + part[1][d] + part[2][d] + part[3][d];
    __syncthreads();
    if (threadIdx.x < NCLS) {
        int c = threadIdx.x;
        float l = dec_b[c];
#pragma unroll
        for (int e = 0; e < HID; ++e) l += root[e] * dec_w[e * NCLS + c];
        out[c] = l;
    }
}

// ---------------- launcher ----------------
extern "C" void kernel_launch(void *const *d_in, const int *in_sizes, int n_in,
                              void *d_out, int out_size) {
    const float *adj   = (const float *)d_in[0];
    const float *tfidf = (const float *)d_in[1];
    const int   *level = (const int *)d_in[2];
    const float *E     = (const float *)d_in[3];
    const float *Wr    = (const float *)d_in[4];
    const float *Wz    = (const float *)d_in[5];
    const float *Ur    = (const float *)d_in[6];
    const float *Uz    = (const float *)d_in[7];
    const float *Wh    = (const float *)d_in[8];
    const float *Uh    = (const float *)d_in[9];
    const float *dec_w = (const float *)d_in[10];
    const float *dec_b = (const float *)d_in[11];
    float *out = (float *)d_out;

    k_zero<<<(NN * HID / 4) / 256, 256>>>();
    k_order<<<1, 1024>>>(level);
    k_emb<<<NN / 64, 128>>>(tfidf, E);
    k_gates<<<NN / 4, 256>>>(Wr, Wz, Wh);
    for (int j = NLEV - 1; j >= 0; --j) {
        k_hs<<<dim3(NN / 64, HS_SPLIT), 128>>>(adj, j);
        k_gru<<<NN / 4, 256>>>(Ur, Uz, Uh, j);
    }
    k_root<<<1, 256>>>(level, dec_w, dec_b, out);
}

// round 2
// speedup vs baseline: 1.8689x; 1.8689x over previous
#include <cuda_runtime.h>
#include <math.h>

#define NN      16384
#define IN_DIM  5000
#define HID     64
#define NCLS    4
#define NLEV    11
#define SPLIT   16
#define KSEG    (NN / SPLIT)
#define PAD     72

// ---------------- scratch (device globals; no allocation) ----------------
__device__ float g_h[NN * HID];                      // rounded-to-tf32 hidden state (by node id)
__device__ float g_xr[NN * HID];
__device__ float g_xz[NN * HID];
__device__ float g_xh[NN * HID];
__device__ float g_hsp[(size_t)SPLIT * NN * HID];    // 64 MB k-split partial hs (by compact t)
__device__ float g_rootp[64 * HID];
__device__ int   g_order[NN];
__device__ int   g_segbase[NLEV];
__device__ int   g_cnt[NLEV];

// round fp32 to tf32 (nearest, half-up) so HMMA's truncation is exact -> unbiased
__device__ __forceinline__ float rnd_tf32(float x) {
    unsigned u = __float_as_uint(x);
    u = (u + 0x1000u) & 0xFFFFE000u;
    return __uint_as_float(u);
}

__device__ __forceinline__ void mma_tf32(float c[4], const unsigned a[4], const unsigned b[2]) {
    asm volatile(
        "mma.sync.aligned.m16n8k8.row.col.f32.tf32.tf32.f32 "
        "{%0,%1,%2,%3}, {%4,%5,%6,%7}, {%8,%9}, {%0,%1,%2,%3};"
        : "+f"(c[0]), "+f"(c[1]), "+f"(c[2]), "+f"(c[3])
        : "r"(a[0]), "r"(a[1]), "r"(a[2]), "r"(a[3]), "r"(b[0]), "r"(b[1]));
}

// ---------------- zero hidden state ----------------
__global__ void k_zero() {
    size_t i = (size_t)blockIdx.x * blockDim.x + threadIdx.x;
    *(float4 *)(g_h + 4 * i) = make_float4(0.f, 0.f, 0.f, 0.f);
}

// ---------------- deterministic bucket sort by level (desc segments, stable by id) ----------------
__global__ __launch_bounds__(1024) void k_order(const int *__restrict__ level) {
    __shared__ int cnt[NLEV][1024];
    __shared__ int sb[NLEV];
    const int t = threadIdx.x;
    int loc[NLEV];
#pragma unroll
    for (int j = 0; j < NLEV; ++j) loc[j] = 0;
    const int base = t * 16;
    int lv[16];
#pragma unroll
    for (int i = 0; i < 16; ++i) { lv[i] = level[base + i]; loc[lv[i]]++; }
#pragma unroll
    for (int j = 0; j < NLEV; ++j) cnt[j][t] = loc[j];
    __syncthreads();
    // inclusive scans per level
    for (int j = 0; j < NLEV; ++j) {
        for (int off = 1; off < 1024; off <<= 1) {
            int v = (t >= off) ? cnt[j][t - off] : 0;
            __syncthreads();
            cnt[j][t] += v;
            __syncthreads();
        }
    }
    if (t == 0) {
        int acc = 0;
        for (int j = NLEV - 1; j >= 0; --j) {
            sb[j] = acc;
            g_segbase[j] = acc;
            g_cnt[j] = cnt[j][1023];
            acc += cnt[j][1023];
        }
    }
    __syncthreads();
    int off[NLEV];
#pragma unroll
    for (int j = 0; j < NLEV; ++j) off[j] = sb[j] + cnt[j][t] - loc[j];
#pragma unroll
    for (int i = 0; i < 16; ++i) g_order[off[lv[i]]++] = base + i;
}

// ---------------- tf32 mma tile core: one warp computes 16x64 of C += A(64xKT) B(KTx64) ----------------
// As[row][k], Bs[k][n], both stride PAD=72 (conflict-free frag loads)
__device__ __forceinline__ void mma_block(const float (*As)[PAD], const float (*Bs)[PAD],
                                          float c[8][4], int w, int gid, int tig) {
    const float *pA = &As[w * 16 + gid][tig];
    const float *pB = &Bs[tig][gid];
#pragma unroll
    for (int kc = 0; kc < 8; ++kc) {
        unsigned a[4];
        a[0] = __float_as_uint(pA[kc * 8]);
        a[1] = __float_as_uint(pA[8 * PAD + kc * 8]);
        a[2] = __float_as_uint(pA[kc * 8 + 4]);
        a[3] = __float_as_uint(pA[8 * PAD + kc * 8 + 4]);
#pragma unroll
        for (int nt = 0; nt < 8; ++nt) {
            unsigned b[2];
            b[0] = __float_as_uint(pB[kc * 8 * PAD + nt * 8]);
            b[1] = __float_as_uint(pB[(kc * 8 + 4) * PAD + nt * 8]);
            mma_tf32(c[nt], a, b);
        }
    }
}

// ---------------- embedding GEMM + fused gate projections ----------------
__global__ __launch_bounds__(128, 4) void k_emb(const float *__restrict__ A, const float *__restrict__ E,
                                                const float *__restrict__ Wr, const float *__restrict__ Wz,
                                                const float *__restrict__ Wh) {
    __shared__ float As[64][PAD];
    __shared__ float Bs[64][PAD];
    const int tid = threadIdx.x;
    const int row0 = blockIdx.x * 64;
    const int w = tid >> 5, lane = tid & 31, gid = lane >> 2, tig = lane & 3;
    float c[8][4];
#pragma unroll
    for (int nt = 0; nt < 8; ++nt)
#pragma unroll
        for (int i = 0; i < 4; ++i) c[nt][i] = 0.f;

    for (int k0 = 0; k0 < IN_DIM; k0 += 64) {
        float4 sa[8], sbv[8];
#pragma unroll
        for (int v = 0; v < 8; ++v) {
            int pidx = tid + 128 * v;
            int r = pidx >> 4, kq = pidx & 15;
            int k = k0 + kq * 4;
            sa[v] = (k < IN_DIM) ? *(const float4 *)(A + (size_t)(row0 + r) * IN_DIM + k)
                                 : make_float4(0.f, 0.f, 0.f, 0.f);
            int kb = k0 + r;
            sbv[v] = (kb < IN_DIM) ? *(const float4 *)(E + (size_t)kb * HID + kq * 4)
                                   : make_float4(0.f, 0.f, 0.f, 0.f);
        }
        __syncthreads();
#pragma unroll
        for (int v = 0; v < 8; ++v) {
            int pidx = tid + 128 * v;
            int r = pidx >> 4, kq = pidx & 15;
            As[r][kq * 4 + 0] = rnd_tf32(sa[v].x);
            As[r][kq * 4 + 1] = rnd_tf32(sa[v].y);
            As[r][kq * 4 + 2] = rnd_tf32(sa[v].z);
            As[r][kq * 4 + 3] = rnd_tf32(sa[v].w);
            Bs[r][kq * 4 + 0] = rnd_tf32(sbv[v].x);
            Bs[r][kq * 4 + 1] = rnd_tf32(sbv[v].y);
            Bs[r][kq * 4 + 2] = rnd_tf32(sbv[v].z);
            Bs[r][kq * 4 + 3] = rnd_tf32(sbv[v].w);
        }
        __syncthreads();
        mma_block(As, Bs, c, w, gid, tig);
    }

    // write x_hat tile (rounded) into As, then 3 gate GEMMs over K=64
    __syncthreads();
#pragma unroll
    for (int nt = 0; nt < 8; ++nt) {
        int col = nt * 8 + tig * 2;
        As[w * 16 + gid][col] = rnd_tf32(c[nt][0]);
        As[w * 16 + gid][col + 1] = rnd_tf32(c[nt][1]);
        As[w * 16 + gid + 8][col] = rnd_tf32(c[nt][2]);
        As[w * 16 + gid + 8][col + 1] = rnd_tf32(c[nt][3]);
    }
    __syncthreads();

    for (int g = 0; g < 3; ++g) {
        const float *W = (g == 0) ? Wr : ((g == 1) ? Wz : Wh);
        float *dst = (g == 0) ? g_xr : ((g == 1) ? g_xz : g_xh);
#pragma unroll
        for (int v = 0; v < 8; ++v) {
            int pidx = tid + 128 * v;
            int r = pidx >> 4, kq = pidx & 15;
            float4 wv = *(const float4 *)(W + r * HID + kq * 4);
            Bs[r][kq * 4 + 0] = rnd_tf32(wv.x);
            Bs[r][kq * 4 + 1] = rnd_tf32(wv.y);
            Bs[r][kq * 4 + 2] = rnd_tf32(wv.z);
            Bs[r][kq * 4 + 3] = rnd_tf32(wv.w);
        }
        __syncthreads();
        float cg[8][4];
#pragma unroll
        for (int nt = 0; nt < 8; ++nt)
#pragma unroll
            for (int i = 0; i < 4; ++i) cg[nt][i] = 0.f;
        mma_block(As, Bs, cg, w, gid, tig);
#pragma unroll
        for (int nt = 0; nt < 8; ++nt) {
            int col = nt * 8 + tig * 2;
            size_t r1 = (size_t)(row0 + w * 16 + gid) * HID;
            size_t r2 = (size_t)(row0 + w * 16 + gid + 8) * HID;
            *(float2 *)(dst + r1 + col) = make_float2(cg[nt][0], cg[nt][1]);
            *(float2 *)(dst + r2 + col) = make_float2(cg[nt][2], cg[nt][3]);
        }
        __syncthreads();
    }
}

// ---------------- hs partial GEMM for one level: hs[t] += adj[node_t, kseg] @ h[kseg] ----------------
__global__ __launch_bounds__(128, 4) void k_hs(const float *__restrict__ adj, int lev) {
    __shared__ float As[64][PAD];
    __shared__ float Hs[64][PAD];
    __shared__ int rowNode[64];
    const int segbase = g_segbase[lev];
    const int cnt = g_cnt[lev];
    const int rb = blockIdx.x * 64;
    if (rb >= cnt) return;
    const int nrows = min(64, cnt - rb);
    const int tid = threadIdx.x;
    if (tid < 64) rowNode[tid] = g_order[segbase + ((tid < nrows) ? rb + tid : rb + nrows - 1)];
    __syncthreads();
    const int split = blockIdx.y;
    const int kb = split * KSEG;
    const int w = tid >> 5, lane = tid & 31, gid = lane >> 2, tig = lane & 3;
    float c[8][4];
#pragma unroll
    for (int nt = 0; nt < 8; ++nt)
#pragma unroll
        for (int i = 0; i < 4; ++i) c[nt][i] = 0.f;

    for (int k0 = kb; k0 < kb + KSEG; k0 += 64) {
        float4 sa[8], sh[8];
#pragma unroll
        for (int v = 0; v < 8; ++v) {
            int pidx = tid + 128 * v;
            int r = pidx >> 4, kq = pidx & 15;
            sa[v] = *(const float4 *)(adj + (size_t)rowNode[r] * NN + k0 + kq * 4);
            sh[v] = *(const float4 *)(g_h + (size_t)(k0 + r) * HID + kq * 4);
        }
        __syncthreads();
#pragma unroll
        for (int v = 0; v < 8; ++v) {
            int pidx = tid + 128 * v;
            int r = pidx >> 4, kq = pidx & 15;
            As[r][kq * 4 + 0] = rnd_tf32(sa[v].x);
            As[r][kq * 4 + 1] = rnd_tf32(sa[v].y);
            As[r][kq * 4 + 2] = rnd_tf32(sa[v].z);
            As[r][kq * 4 + 3] = rnd_tf32(sa[v].w);
            // h already rounded at write time
            *(float4 *)&Hs[r][kq * 4] = sh[v];
        }
        __syncthreads();
        mma_block(As, Hs, c, w, gid, tig);
    }

#pragma unroll
    for (int nt = 0; nt < 8; ++nt) {
        int col = nt * 8 + tig * 2;
        int r1 = w * 16 + gid, r2 = r1 + 8;
        if (r1 < nrows) {
            size_t t1 = (size_t)segbase + rb + r1;
            *(float2 *)(g_hsp + ((size_t)split * NN + t1) * HID + col) = make_float2(c[nt][0], c[nt][1]);
        }
        if (r2 < nrows) {
            size_t t2 = (size_t)segbase + rb + r2;
            *(float2 *)(g_hsp + ((size_t)split * NN + t2) * HID + col) = make_float2(c[nt][2], c[nt][3]);
        }
    }
}

// ---------------- GRU cell for one level ----------------
__global__ void k_gru(const float *__restrict__ Ur, const float *__restrict__ Uz,
                      const float *__restrict__ Uh, int lev) {
    __shared__ float hsS[4][HID];
    __shared__ float hrS[4][HID];
    const int segbase = g_segbase[lev];
    const int cnt = g_cnt[lev];
    if (blockIdx.x * 4 >= cnt) return;
    const int r = threadIdx.x >> 6;
    const int d = threadIdx.x & 63;
    const int ridx = blockIdx.x * 4 + r;
    const bool act = ridx < cnt;
    const size_t t = (size_t)segbase + (act ? ridx : (cnt - 1));
    const int node = g_order[t];
    float hsv = 0.f;
#pragma unroll
    for (int s = 0; s < SPLIT; ++s) hsv += g_hsp[((size_t)s * NN + t) * HID + d];
    hsS[r][d] = hsv;
    __syncthreads();
    float rr = g_xr[(size_t)node * HID + d];
    float zz = g_xz[(size_t)node * HID + d];
#pragma unroll
    for (int e = 0; e < HID; ++e) {
        float he = hsS[r][e];
        rr += he * Ur[e * HID + d];
        zz += he * Uz[e * HID + d];
    }
    rr = 1.f / (1.f + expf(-rr));
    zz = 1.f / (1.f + expf(-zz));
    hrS[r][d] = hsv * rr;
    __syncthreads();
    float hh = g_xh[(size_t)node * HID + d];
#pragma unroll
    for (int e = 0; e < HID; ++e) hh += hrS[r][e] * Uh[e * HID + d];
    hh = tanhf(hh);
    if (act) g_h[(size_t)node * HID + d] = rnd_tf32((1.f - zz) * hsv + zz * hh);
}

// ---------------- root readout (2-stage, deterministic by node id) ----------------
__global__ void k_root1(const int *__restrict__ level) {
    __shared__ float p[4][HID];
    const int g = threadIdx.x >> 6;
    const int d = threadIdx.x & 63;
    const int base = blockIdx.x * 256;
    float s = 0.f;
    for (int i = base + g; i < base + 256; i += 4)
        if (level[i] == 0) s += g_h[(size_t)i * HID + d];
    p[g][d] = s;
    __syncthreads();
    if (g == 0) g_rootp[blockIdx.x * HID + d] = p[0][d] + p[1][d] + p[2][d] + p[3][d];
}

__global__ void k_root2(const float *__restrict__ dec_w, const float *__restrict__ dec_b,
                        float *__restrict__ out) {
    __shared__ float root[HID];
    const int d = threadIdx.x;
    float s = 0.f;
#pragma unroll
    for (int b = 0; b < 64; ++b) s += g_rootp[b * HID + d];
    root[d] = s;
    __syncthreads();
    if (d < NCLS) {
        float l = dec_b[d];
#pragma unroll
        for (int e = 0; e < HID; ++e) l += root[e] * dec_w[e * NCLS + d];
        out[d] = l;
    }
}

// ---------------- launcher ----------------
extern "C" void kernel_launch(void *const *d_in, const int *in_sizes, int n_in,
                              void *d_out, int out_size) {
    const float *adj   = (const float *)d_in[0];
    const float *tfidf = (const float *)d_in[1];
    const int   *level = (const int *)d_in[2];
    const float *E     = (const float *)d_in[3];
    const float *Wr    = (const float *)d_in[4];
    const float *Wz    = (const float *)d_in[5];
    const float *Ur    = (const float *)d_in[6];
    const float *Uz    = (const float *)d_in[7];
    const float *Wh    = (const float *)d_in[8];
    const float *Uh    = (const float *)d_in[9];
    const float *dec_w = (const float *)d_in[10];
    const float *dec_b = (const float *)d_in[11];
    float *out = (float *)d_out;

    k_zero<<<(NN * HID / 4) / 256, 256>>>();
    k_order<<<1, 1024>>>(level);
    k_emb<<<NN / 64, 128>>>(tfidf, E, Wr, Wz, Wh);
    for (int j = NLEV - 1; j >= 0; --j) {
        k_hs<<<dim3(NN / 64, SPLIT), 128>>>(adj, j);
        k_gru<<<NN / 4, 256>>>(Ur, Uz, Uh, j);
    }
    k_root1<<<64, 256>>>(level);
    k_root2<<<1, 64>>>(dec_w, dec_b, out);
}

// round 3
// speedup vs baseline: 2.7839x; 1.4896x over previous
#include <cuda_runtime.h>
#include <math.h>

#define NN      16384
#define IN_DIM  5000
#define HID     64
#define NCLS    4
#define NLEV    11
#define SPLIT   32
#define KSEG    (NN / SPLIT)   // 512
#define NT_HS   (KSEG / 32)    // 16
#define AP      36             // A-tile pitch (floats): 128 rows x 32 k
#define BP      72             // B-tile pitch: 32 k x 64 n
#define XP      68             // x_hat tile pitch
#define SMEMSZ  55296
#define MAXROWB 24             // row-blocks launched per level (covers cnt<=3072)

// ---------------- scratch ----------------
__device__ float g_h[NN * HID];
__device__ float g_xr[NN * HID];
__device__ float g_xz[NN * HID];
__device__ float g_xh[NN * HID];
__device__ float g_hsp[(size_t)SPLIT * NN * HID];
__device__ float g_rootp[64 * HID];
__device__ int   g_order[NN];
__device__ int   g_segbase[NLEV];
__device__ int   g_cnt[NLEV];

__device__ __forceinline__ unsigned rndu(unsigned u) { return (u + 0x1000u) & 0xFFFFE000u; }
__device__ __forceinline__ float rnd_tf32(float x) { return __uint_as_float(rndu(__float_as_uint(x))); }

__device__ __forceinline__ void mma_tf32(float c[4], const unsigned a[4], const unsigned b[2]) {
    asm volatile(
        "mma.sync.aligned.m16n8k8.row.col.f32.tf32.tf32.f32 "
        "{%0,%1,%2,%3}, {%4,%5,%6,%7}, {%8,%9}, {%0,%1,%2,%3};"
        : "+f"(c[0]), "+f"(c[1]), "+f"(c[2]), "+f"(c[3])
        : "r"(a[0]), "r"(a[1]), "r"(a[2]), "r"(a[3]), "r"(b[0]), "r"(b[1]));
}

__device__ __forceinline__ void cpa16(void *s, const void *g, bool full) {
    unsigned sa = (unsigned)__cvta_generic_to_shared(s);
    int n = full ? 16 : 0;
    asm volatile("cp.async.cg.shared.global [%0],[%1],16,%2;" ::"r"(sa), "l"(g), "r"(n));
}
__device__ __forceinline__ void cp_commit() { asm volatile("cp.async.commit_group;"); }
__device__ __forceinline__ void cp_wait1() { asm volatile("cp.async.wait_group 1;" ::: "memory"); }
__device__ __forceinline__ void cp_wait0() { asm volatile("cp.async.wait_group 0;" ::: "memory"); }

// ---- warp MMA: 32 rows x 64 cols, b-fragments hoisted/reused across both row-groups ----
// As points at warp's row base (pitch APitch), Bs at B tile base (pitch BPitch, [k][n])
template <int APitch, int BPitch, int NKC, bool RA, bool RB>
__device__ __forceinline__ void mm_warp(const float *__restrict__ As, const float *__restrict__ Bs,
                                        float (&c)[2][8][4], int gid, int tig) {
    const float *pA = As + gid * APitch + tig;
    const float *pB = Bs + tig * BPitch + gid;
#pragma unroll
    for (int kc = 0; kc < NKC; ++kc) {
        unsigned b[8][2];
#pragma unroll
        for (int nt = 0; nt < 8; ++nt) {
            b[nt][0] = __float_as_uint(pB[(kc * 8) * BPitch + nt * 8]);
            b[nt][1] = __float_as_uint(pB[(kc * 8 + 4) * BPitch + nt * 8]);
            if (RB) { b[nt][0] = rndu(b[nt][0]); b[nt][1] = rndu(b[nt][1]); }
        }
#pragma unroll
        for (int h = 0; h < 2; ++h) {
            const float *q = pA + h * 16 * APitch + kc * 8;
            unsigned a[4];
            a[0] = __float_as_uint(q[0]);
            a[1] = __float_as_uint(q[8 * APitch]);
            a[2] = __float_as_uint(q[4]);
            a[3] = __float_as_uint(q[8 * APitch + 4]);
            if (RA) {
#pragma unroll
                for (int i = 0; i < 4; ++i) a[i] = rndu(a[i]);
            }
#pragma unroll
            for (int nt = 0; nt < 8; ++nt) mma_tf32(c[h][nt], a, b[nt]);
        }
    }
}

// ---------------- zero hidden state ----------------
__global__ void k_zero() {
    size_t i = (size_t)blockIdx.x * blockDim.x + threadIdx.x;
    *(float4 *)(g_h + 4 * i) = make_float4(0.f, 0.f, 0.f, 0.f);
}

// ---------------- deterministic bucket sort by level (warp-scan version) ----------------
__global__ __launch_bounds__(1024) void k_order(const int *__restrict__ level) {
    __shared__ int cnt[NLEV][1024];
    __shared__ int sb[NLEV];
    const int t = threadIdx.x;
    const int base = t * 16;
    int lv[16], loc[NLEV];
#pragma unroll
    for (int j = 0; j < NLEV; ++j) loc[j] = 0;
#pragma unroll
    for (int i = 0; i < 16; ++i) { lv[i] = level[base + i]; ++loc[lv[i]]; }
#pragma unroll
    for (int j = 0; j < NLEV; ++j) cnt[j][t] = loc[j];
    __syncthreads();
    const int w = t >> 5, lane = t & 31;
    if (w < NLEV) {
        int s = 0;
        for (int i = 0; i < 32; ++i) s += cnt[w][lane * 32 + i];
        int incl = s;
        for (int off = 1; off < 32; off <<= 1) {
            int n = __shfl_up_sync(0xffffffffu, incl, off);
            if (lane >= off) incl += n;
        }
        int run = incl - s;
        for (int i = 0; i < 32; ++i) { run += cnt[w][lane * 32 + i]; cnt[w][lane * 32 + i] = run; }
    }
    __syncthreads();
    if (t == 0) {
        int acc = 0;
        for (int j = NLEV - 1; j >= 0; --j) {
            sb[j] = acc;
            g_segbase[j] = acc;
            g_cnt[j] = cnt[j][1023];
            acc += cnt[j][1023];
        }
    }
    __syncthreads();
    int off[NLEV];
#pragma unroll
    for (int j = 0; j < NLEV; ++j) off[j] = sb[j] + cnt[j][t] - loc[j];
#pragma unroll
    for (int i = 0; i < 16; ++i) g_order[off[lv[i]]++] = base + i;
}

// ---------------- embedding GEMM + fused gate projections (pipelined) ----------------
__global__ __launch_bounds__(128) void k_emb(const float *__restrict__ A, const float *__restrict__ E,
                                             const float *__restrict__ Wr, const float *__restrict__ Wz,
                                             const float *__restrict__ Wh) {
    extern __shared__ float sp[];
    float *Asb = sp;                   // 2 stages x 128*AP
    float *Bsb = sp + 2 * 128 * AP;    // 2 stages x 32*BP
    const int t = threadIdx.x, row0 = blockIdx.x * 128;
    const int w = t >> 5, lane = t & 31, gid = lane >> 2, tig = lane & 3;
    const int NT = (IN_DIM + 31) / 32;  // 157

    auto issue = [&](int it) {
        const int s = it & 1, k0 = it * 32;
        float *As = Asb + s * 128 * AP;
        float *Bs = Bsb + s * 32 * BP;
#pragma unroll
        for (int v = 0; v < 8; ++v) {
            int p = t + 128 * v;
            int r = p >> 3, ch = p & 7;
            int gc = k0 + ch * 4;
            bool ok = gc < IN_DIM;
            cpa16(&As[r * AP + ch * 4], A + (size_t)(row0 + r) * IN_DIM + (ok ? gc : 0), ok);
        }
#pragma unroll
        for (int v = 0; v < 4; ++v) {
            int p = t + 128 * v;
            int r = p >> 4, ch = p & 15;
            int gr = k0 + r;
            bool ok = gr < IN_DIM;
            cpa16(&Bs[r * BP + ch * 4], E + (size_t)(ok ? gr : 0) * HID + ch * 4, ok);
        }
        cp_commit();
    };

    float c[2][8][4];
#pragma unroll
    for (int h = 0; h < 2; ++h)
#pragma unroll
        for (int nt = 0; nt < 8; ++nt)
#pragma unroll
            for (int i = 0; i < 4; ++i) c[h][nt][i] = 0.f;

    issue(0);
    for (int it = 0; it < NT; ++it) {
        if (it + 1 < NT) { issue(it + 1); cp_wait1(); } else cp_wait0();
        __syncthreads();
        const int s = it & 1;
        mm_warp<AP, BP, 4, true, true>(Asb + s * 128 * AP + (w * 32) * AP, Bsb + s * 32 * BP, c, gid, tig);
        __syncthreads();
    }

    // x_hat (rounded) -> Xs, then 3 gate GEMMs
    float *Xs = sp;                // 128*XP
    float *Ws = sp + 128 * XP;     // 64*BP
#pragma unroll
    for (int h = 0; h < 2; ++h)
#pragma unroll
        for (int nt = 0; nt < 8; ++nt) {
            int col = nt * 8 + tig * 2;
            int r1 = w * 32 + h * 16 + gid, r2 = r1 + 8;
            Xs[r1 * XP + col] = rnd_tf32(c[h][nt][0]);
            Xs[r1 * XP + col + 1] = rnd_tf32(c[h][nt][1]);
            Xs[r2 * XP + col] = rnd_tf32(c[h][nt][2]);
            Xs[r2 * XP + col + 1] = rnd_tf32(c[h][nt][3]);
        }
    for (int g = 0; g < 3; ++g) {
        const float *W = (g == 0) ? Wr : ((g == 1) ? Wz : Wh);
        float *dst = (g == 0) ? g_xr : ((g == 1) ? g_xz : g_xh);
        __syncthreads();
#pragma unroll
        for (int v = 0; v < 8; ++v) {
            int p = t + 128 * v;
            int r = p >> 4, ch = p & 15;
            float4 wv = *(const float4 *)(W + r * HID + ch * 4);
            Ws[r * BP + ch * 4 + 0] = rnd_tf32(wv.x);
            Ws[r * BP + ch * 4 + 1] = rnd_tf32(wv.y);
            Ws[r * BP + ch * 4 + 2] = rnd_tf32(wv.z);
            Ws[r * BP + ch * 4 + 3] = rnd_tf32(wv.w);
        }
        __syncthreads();
        float cg[2][8][4];
#pragma unroll
        for (int h = 0; h < 2; ++h)
#pragma unroll
            for (int nt = 0; nt < 8; ++nt)
#pragma unroll
                for (int i = 0; i < 4; ++i) cg[h][nt][i] = 0.f;
        mm_warp<XP, BP, 8, false, false>(Xs + (w * 32) * XP, Ws, cg, gid, tig);
#pragma unroll
        for (int h = 0; h < 2; ++h)
#pragma unroll
            for (int nt = 0; nt < 8; ++nt) {
                int col = nt * 8 + tig * 2;
                size_t r1 = (size_t)(row0 + w * 32 + h * 16 + gid) * HID;
                size_t r2 = r1 + 8 * HID;
                *(float2 *)(dst + r1 + col) = make_float2(cg[h][nt][0], cg[h][nt][1]);
                *(float2 *)(dst + r2 + col) = make_float2(cg[h][nt][2], cg[h][nt][3]);
            }
    }
}

// ---------------- hs partial GEMM (pipelined): hs[t] = adj[node_t, kseg] @ h[kseg] ----------------
__global__ __launch_bounds__(128) void k_hs(const float *__restrict__ adj, int lev) {
    extern __shared__ float sp[];
    float *Asb = sp;
    float *Bsb = sp + 2 * 128 * AP;
    __shared__ int rowNode[128];
    const int segbase = g_segbase[lev], cnt = g_cnt[lev];
    const int rb = blockIdx.x * 128;
    if (rb >= cnt) return;
    const int nrows = min(128, cnt - rb);
    const int t = threadIdx.x;
    rowNode[t] = g_order[segbase + ((t < nrows) ? rb + t : rb + nrows - 1)];
    __syncthreads();
    const int kb = blockIdx.y * KSEG;
    const int w = t >> 5, lane = t & 31, gid = lane >> 2, tig = lane & 3;

    auto issue = [&](int it) {
        const int s = it & 1;
        const int k0 = kb + it * 32;
        float *As = Asb + s * 128 * AP;
        float *Bs = Bsb + s * 32 * BP;
#pragma unroll
        for (int v = 0; v < 8; ++v) {
            int p = t + 128 * v;
            int r = p >> 3, ch = p & 7;
            cpa16(&As[r * AP + ch * 4], adj + (size_t)rowNode[r] * NN + k0 + ch * 4, true);
        }
#pragma unroll
        for (int v = 0; v < 4; ++v) {
            int p = t + 128 * v;
            int r = p >> 4, ch = p & 15;
            cpa16(&Bs[r * BP + ch * 4], g_h + (size_t)(k0 + r) * HID + ch * 4, true);
        }
        cp_commit();
    };

    float c[2][8][4];
#pragma unroll
    for (int h = 0; h < 2; ++h)
#pragma unroll
        for (int nt = 0; nt < 8; ++nt)
#pragma unroll
            for (int i = 0; i < 4; ++i) c[h][nt][i] = 0.f;

    issue(0);
    for (int it = 0; it < NT_HS; ++it) {
        if (it + 1 < NT_HS) { issue(it + 1); cp_wait1(); } else cp_wait0();
        __syncthreads();
        const int s = it & 1;
        // adj rounded at fragment load; h pre-rounded at write time
        mm_warp<AP, BP, 4, true, false>(Asb + s * 128 * AP + (w * 32) * AP, Bsb + s * 32 * BP, c, gid, tig);
        __syncthreads();
    }

    const size_t base = (size_t)blockIdx.y * NN + segbase + rb;
#pragma unroll
    for (int h = 0; h < 2; ++h)
#pragma unroll
        for (int nt = 0; nt < 8; ++nt) {
            int col = nt * 8 + tig * 2;
            int r1 = w * 32 + h * 16 + gid, r2 = r1 + 8;
            if (r1 < nrows)
                *(float2 *)(g_hsp + (base + r1) * HID + col) = make_float2(c[h][nt][0], c[h][nt][1]);
            if (r2 < nrows)
                *(float2 *)(g_hsp + (base + r2) * HID + col) = make_float2(c[h][nt][2], c[h][nt][3]);
        }
}

// ---------------- GRU cell for one level ----------------
__global__ void k_gru(const float *__restrict__ Ur, const float *__restrict__ Uz,
                      const float *__restrict__ Uh, int lev) {
    __shared__ float hsS[4][HID];
    __shared__ float hrS[4][HID];
    const int segbase = g_segbase[lev];
    const int cnt = g_cnt[lev];
    if (blockIdx.x * 4 >= cnt) return;
    const int r = threadIdx.x >> 6;
    const int d = threadIdx.x & 63;
    const int ridx = blockIdx.x * 4 + r;
    const bool act = ridx < cnt;
    const size_t tt = (size_t)segbase + (act ? ridx : (cnt - 1));
    const int node = g_order[tt];
    float hsv = 0.f;
#pragma unroll
    for (int s = 0; s < SPLIT; ++s) hsv += g_hsp[((size_t)s * NN + tt) * HID + d];
    hsS[r][d] = hsv;
    __syncthreads();
    float rr = g_xr[(size_t)node * HID + d];
    float zz = g_xz[(size_t)node * HID + d];
#pragma unroll
    for (int e = 0; e < HID; ++e) {
        float he = hsS[r][e];
        rr += he * Ur[e * HID + d];
        zz += he * Uz[e * HID + d];
    }
    rr = 1.f / (1.f + expf(-rr));
    zz = 1.f / (1.f + expf(-zz));
    hrS[r][d] = hsv * rr;
    __syncthreads();
    float hh = g_xh[(size_t)node * HID + d];
#pragma unroll
    for (int e = 0; e < HID; ++e) hh += hrS[r][e] * Uh[e * HID + d];
    hh = tanhf(hh);
    if (act) g_h[(size_t)node * HID + d] = rnd_tf32((1.f - zz) * hsv + zz * hh);
}

// ---------------- root readout ----------------
__global__ void k_root1(const int *__restrict__ level) {
    __shared__ float p[4][HID];
    const int g = threadIdx.x >> 6;
    const int d = threadIdx.x & 63;
    const int base = blockIdx.x * 256;
    float s = 0.f;
    for (int i = base + g; i < base + 256; i += 4)
        if (level[i] == 0) s += g_h[(size_t)i * HID + d];
    p[g][d] = s;
    __syncthreads();
    if (g == 0) g_rootp[blockIdx.x * HID + d] = p[0][d] + p[1][d] + p[2][d] + p[3][d];
}

__global__ void k_root2(const float *__restrict__ dec_w, const float *__restrict__ dec_b,
                        float *__restrict__ out) {
    __shared__ float root[HID];
    const int d = threadIdx.x;
    float s = 0.f;
#pragma unroll
    for (int b = 0; b < 64; ++b) s += g_rootp[b * HID + d];
    root[d] = s;
    __syncthreads();
    if (d < NCLS) {
        float l = dec_b[d];
#pragma unroll
        for (int e = 0; e < HID; ++e) l += root[e] * dec_w[e * NCLS + d];
        out[d] = l;
    }
}

// ---------------- launcher ----------------
extern "C" void kernel_launch(void *const *d_in, const int *in_sizes, int n_in,
                              void *d_out, int out_size) {
    const float *adj   = (const float *)d_in[0];
    const float *tfidf = (const float *)d_in[1];
    const int   *level = (const int *)d_in[2];
    const float *E     = (const float *)d_in[3];
    const float *Wr    = (const float *)d_in[4];
    const float *Wz    = (const float *)d_in[5];
    const float *Ur    = (const float *)d_in[6];
    const float *Uz    = (const float *)d_in[7];
    const float *Wh    = (const float *)d_in[8];
    const float *Uh    = (const float *)d_in[9];
    const float *dec_w = (const float *)d_in[10];
    const float *dec_b = (const float *)d_in[11];
    float *out = (float *)d_out;

    cudaFuncSetAttribute(k_hs, cudaFuncAttributeMaxDynamicSharedMemorySize, SMEMSZ);
    cudaFuncSetAttribute(k_emb, cudaFuncAttributeMaxDynamicSharedMemorySize, SMEMSZ);

    k_zero<<<(NN * HID / 4) / 256, 256>>>();
    k_order<<<1, 1024>>>(level);
    k_emb<<<NN / 128, 128, SMEMSZ>>>(tfidf, E, Wr, Wz, Wh);
    for (int j = NLEV - 1; j >= 0; --j) {
        k_hs<<<dim3(MAXROWB, SPLIT), 128, SMEMSZ>>>(adj, j);
        k_gru<<<(MAXROWB * 128) / 4, 256>>>(Ur, Uz, Uh, j);
    }
    k_root1<<<64, 256>>>(level);
    k_root2<<<1, 64>>>(dec_w, dec_b, out);
}

// round 4
// speedup vs baseline: 2.8224x; 1.0138x over previous
#include <cuda_runtime.h>
#include <math.h>

#define NN      16384
#define IN_DIM  5000
#define HID     64
#define NCLS    4
#define NLEV    11
#define SPLIT   64
#define KSEG    (NN / SPLIT)   // 256
#define NT_HS   (KSEG / 32)    // 8
#define AP      36             // A-tile pitch (floats)
#define BP      72             // B-tile pitch: 32 k x 64 n
#define XP      68             // x_hat tile pitch
#define SMEMSZ  55296
#define MAXROWB 24             // row-blocks launched per level (covers cnt<=3072)

// ---------------- scratch ----------------
__device__ float g_h[NN * HID];
__device__ float g_xr[NN * HID];
__device__ float g_xz[NN * HID];
__device__ float g_xh[NN * HID];
__device__ float g_hsp[(size_t)SPLIT * NN * HID];   // 256 MB
__device__ float g_rootp[64 * HID];
__device__ int   g_order[NN];
__device__ int   g_segbase[NLEV];
__device__ int   g_cnt[NLEV];

__device__ __forceinline__ unsigned rndu(unsigned u) { return (u + 0x1000u) & 0xFFFFE000u; }
__device__ __forceinline__ float rnd_tf32(float x) { return __uint_as_float(rndu(__float_as_uint(x))); }

__device__ __forceinline__ void mma_tf32(float c[4], const unsigned a[4], const unsigned b[2]) {
    asm volatile(
        "mma.sync.aligned.m16n8k8.row.col.f32.tf32.tf32.f32 "
        "{%0,%1,%2,%3}, {%4,%5,%6,%7}, {%8,%9}, {%0,%1,%2,%3};"
        : "+f"(c[0]), "+f"(c[1]), "+f"(c[2]), "+f"(c[3])
        : "r"(a[0]), "r"(a[1]), "r"(a[2]), "r"(a[3]), "r"(b[0]), "r"(b[1]));
}

__device__ __forceinline__ void cpa16(void *s, const void *g, bool full) {
    unsigned sa = (unsigned)__cvta_generic_to_shared(s);
    int n = full ? 16 : 0;
    asm volatile("cp.async.cg.shared.global [%0],[%1],16,%2;" ::"r"(sa), "l"(g), "r"(n));
}
__device__ __forceinline__ void cp_commit() { asm volatile("cp.async.commit_group;"); }
__device__ __forceinline__ void cp_wait1() { asm volatile("cp.async.wait_group 1;" ::: "memory"); }
__device__ __forceinline__ void cp_wait2() { asm volatile("cp.async.wait_group 2;" ::: "memory"); }

// ---- warp MMA: NH*16 rows x 64 cols, b-fragments hoisted/reused across row-groups ----
template <int APitch, int BPitch, int NKC, int NH, bool RA, bool RB>
__device__ __forceinline__ void mm_warp(const float *__restrict__ As, const float *__restrict__ Bs,
                                        float (&c)[NH][8][4], int gid, int tig) {
    const float *pA = As + gid * APitch + tig;
    const float *pB = Bs + tig * BPitch + gid;
#pragma unroll
    for (int kc = 0; kc < NKC; ++kc) {
        unsigned b[8][2];
#pragma unroll
        for (int nt = 0; nt < 8; ++nt) {
            b[nt][0] = __float_as_uint(pB[(kc * 8) * BPitch + nt * 8]);
            b[nt][1] = __float_as_uint(pB[(kc * 8 + 4) * BPitch + nt * 8]);
            if (RB) { b[nt][0] = rndu(b[nt][0]); b[nt][1] = rndu(b[nt][1]); }
        }
#pragma unroll
        for (int h = 0; h < NH; ++h) {
            const float *q = pA + h * 16 * APitch + kc * 8;
            unsigned a[4];
            a[0] = __float_as_uint(q[0]);
            a[1] = __float_as_uint(q[8 * APitch]);
            a[2] = __float_as_uint(q[4]);
            a[3] = __float_as_uint(q[8 * APitch + 4]);
            if (RA) {
#pragma unroll
                for (int i = 0; i < 4; ++i) a[i] = rndu(a[i]);
            }
#pragma unroll
            for (int nt = 0; nt < 8; ++nt) mma_tf32(c[h][nt], a, b[nt]);
        }
    }
}

// ---------------- zero hidden state ----------------
__global__ void k_zero() {
    size_t i = (size_t)blockIdx.x * blockDim.x + threadIdx.x;
    *(float4 *)(g_h + 4 * i) = make_float4(0.f, 0.f, 0.f, 0.f);
}

// ---------------- deterministic bucket sort by level ----------------
__global__ __launch_bounds__(1024) void k_order(const int *__restrict__ level) {
    __shared__ int cnt[NLEV][1024];
    __shared__ int sb[NLEV];
    const int t = threadIdx.x;
    const int base = t * 16;
    int lv[16], loc[NLEV];
#pragma unroll
    for (int j = 0; j < NLEV; ++j) loc[j] = 0;
#pragma unroll
    for (int i = 0; i < 16; ++i) { lv[i] = level[base + i]; ++loc[lv[i]]; }
#pragma unroll
    for (int j = 0; j < NLEV; ++j) cnt[j][t] = loc[j];
    __syncthreads();
    const int w = t >> 5, lane = t & 31;
    if (w < NLEV) {
        int s = 0;
        for (int i = 0; i < 32; ++i) s += cnt[w][lane * 32 + i];
        int incl = s;
        for (int off = 1; off < 32; off <<= 1) {
            int n = __shfl_up_sync(0xffffffffu, incl, off);
            if (lane >= off) incl += n;
        }
        int run = incl - s;
        for (int i = 0; i < 32; ++i) { run += cnt[w][lane * 32 + i]; cnt[w][lane * 32 + i] = run; }
    }
    __syncthreads();
    if (t == 0) {
        int acc = 0;
        for (int j = NLEV - 1; j >= 0; --j) {
            sb[j] = acc;
            g_segbase[j] = acc;
            g_cnt[j] = cnt[j][1023];
            acc += cnt[j][1023];
        }
    }
    __syncthreads();
    int off[NLEV];
#pragma unroll
    for (int j = 0; j < NLEV; ++j) off[j] = sb[j] + cnt[j][t] - loc[j];
#pragma unroll
    for (int i = 0; i < 16; ++i) g_order[off[lv[i]]++] = base + i;
}

// ---------------- embedding GEMM + fused gate projections (64-row tiles, 3-stage) ----------------
__global__ __launch_bounds__(128) void k_emb(const float *__restrict__ A, const float *__restrict__ E,
                                             const float *__restrict__ Wr, const float *__restrict__ Wz,
                                             const float *__restrict__ Wh) {
    extern __shared__ float sp[];
    float *Asb = sp;                  // 3 stages x 64*AP
    float *Bsb = sp + 3 * 64 * AP;    // 3 stages x 32*BP
    const int t = threadIdx.x, row0 = blockIdx.x * 64;
    const int w = t >> 5, lane = t & 31, gid = lane >> 2, tig = lane & 3;
    const int NT = (IN_DIM + 31) / 32;  // 157

    auto issue = [&](int it) {
        if (it >= NT) { cp_commit(); return; }
        const int s = it % 3, k0 = it * 32;
        float *As = Asb + s * 64 * AP;
        float *Bs = Bsb + s * 32 * BP;
#pragma unroll
        for (int v = 0; v < 4; ++v) {
            int p = t + 128 * v;
            int r = p >> 3, ch = p & 7;
            int gc = k0 + ch * 4;
            bool ok = gc < IN_DIM;
            cpa16(&As[r * AP + ch * 4], A + (size_t)(row0 + r) * IN_DIM + (ok ? gc : 0), ok);
        }
#pragma unroll
        for (int v = 0; v < 4; ++v) {
            int p = t + 128 * v;
            int r = p >> 4, ch = p & 15;
            int gr = k0 + r;
            bool ok = gr < IN_DIM;
            cpa16(&Bs[r * BP + ch * 4], E + (size_t)(ok ? gr : 0) * HID + ch * 4, ok);
        }
        cp_commit();
    };

    float c[1][8][4];
#pragma unroll
    for (int nt = 0; nt < 8; ++nt)
#pragma unroll
        for (int i = 0; i < 4; ++i) c[0][nt][i] = 0.f;

    issue(0);
    issue(1);
    for (int it = 0; it < NT; ++it) {
        issue(it + 2);
        cp_wait2();
        __syncthreads();
        const int s = it % 3;
        mm_warp<AP, BP, 4, 1, true, true>(Asb + s * 64 * AP + (w * 16) * AP, Bsb + s * 32 * BP, c, gid, tig);
        __syncthreads();
    }

    // x_hat (rounded) -> Xs, then 3 gate GEMMs over K=64
    float *Xs = sp;               // 64*XP
    float *Ws = sp + 64 * XP;     // 64*BP
#pragma unroll
    for (int nt = 0; nt < 8; ++nt) {
        int col = nt * 8 + tig * 2;
        int r1 = w * 16 + gid, r2 = r1 + 8;
        Xs[r1 * XP + col] = rnd_tf32(c[0][nt][0]);
        Xs[r1 * XP + col + 1] = rnd_tf32(c[0][nt][1]);
        Xs[r2 * XP + col] = rnd_tf32(c[0][nt][2]);
        Xs[r2 * XP + col + 1] = rnd_tf32(c[0][nt][3]);
    }
    for (int g = 0; g < 3; ++g) {
        const float *W = (g == 0) ? Wr : ((g == 1) ? Wz : Wh);
        float *dst = (g == 0) ? g_xr : ((g == 1) ? g_xz : g_xh);
        __syncthreads();
#pragma unroll
        for (int v = 0; v < 8; ++v) {
            int p = t + 128 * v;
            int r = p >> 4, ch = p & 15;
            float4 wv = *(const float4 *)(W + r * HID + ch * 4);
            Ws[r * BP + ch * 4 + 0] = rnd_tf32(wv.x);
            Ws[r * BP + ch * 4 + 1] = rnd_tf32(wv.y);
            Ws[r * BP + ch * 4 + 2] = rnd_tf32(wv.z);
            Ws[r * BP + ch * 4 + 3] = rnd_tf32(wv.w);
        }
        __syncthreads();
        float cg[1][8][4];
#pragma unroll
        for (int nt = 0; nt < 8; ++nt)
#pragma unroll
            for (int i = 0; i < 4; ++i) cg[0][nt][i] = 0.f;
        mm_warp<XP, BP, 8, 1, false, false>(Xs + (w * 16) * XP, Ws, cg, gid, tig);
#pragma unroll
        for (int nt = 0; nt < 8; ++nt) {
            int col = nt * 8 + tig * 2;
            size_t r1 = (size_t)(row0 + w * 16 + gid) * HID;
            size_t r2 = r1 + 8 * HID;
            *(float2 *)(dst + r1 + col) = make_float2(cg[0][nt][0], cg[0][nt][1]);
            *(float2 *)(dst + r2 + col) = make_float2(cg[0][nt][2], cg[0][nt][3]);
        }
    }
}

// ---------------- hs partial GEMM (2-stage, 64-way split) ----------------
__global__ __launch_bounds__(128) void k_hs(const float *__restrict__ adj, int lev) {
    extern __shared__ float sp[];
    float *Asb = sp;                   // 2 stages x 128*AP
    float *Bsb = sp + 2 * 128 * AP;    // 2 stages x 32*BP
    __shared__ int rowNode[128];
    const int segbase = g_segbase[lev], cnt = g_cnt[lev];
    const int rb = blockIdx.x * 128;
    if (rb >= cnt) return;
    const int nrows = min(128, cnt - rb);
    const int t = threadIdx.x;
    rowNode[t] = g_order[segbase + ((t < nrows) ? rb + t : rb + nrows - 1)];
    __syncthreads();
    const int kb = blockIdx.y * KSEG;
    const int w = t >> 5, lane = t & 31, gid = lane >> 2, tig = lane & 3;

    auto issue = [&](int it) {
        if (it >= NT_HS) { cp_commit(); return; }
        const int s = it & 1;
        const int k0 = kb + it * 32;
        float *As = Asb + s * 128 * AP;
        float *Bs = Bsb + s * 32 * BP;
#pragma unroll
        for (int v = 0; v < 8; ++v) {
            int p = t + 128 * v;
            int r = p >> 3, ch = p & 7;
            cpa16(&As[r * AP + ch * 4], adj + (size_t)rowNode[r] * NN + k0 + ch * 4, true);
        }
#pragma unroll
        for (int v = 0; v < 4; ++v) {
            int p = t + 128 * v;
            int r = p >> 4, ch = p & 15;
            cpa16(&Bs[r * BP + ch * 4], g_h + (size_t)(k0 + r) * HID + ch * 4, true);
        }
        cp_commit();
    };

    float c[2][8][4];
#pragma unroll
    for (int h = 0; h < 2; ++h)
#pragma unroll
        for (int nt = 0; nt < 8; ++nt)
#pragma unroll
            for (int i = 0; i < 4; ++i) c[h][nt][i] = 0.f;

    issue(0);
    for (int it = 0; it < NT_HS; ++it) {
        issue(it + 1);
        cp_wait1();
        __syncthreads();
        const int s = it & 1;
        mm_warp<AP, BP, 4, 2, true, false>(Asb + s * 128 * AP + (w * 32) * AP, Bsb + s * 32 * BP, c, gid, tig);
        __syncthreads();
    }

    const size_t base = (size_t)blockIdx.y * NN + segbase + rb;
#pragma unroll
    for (int h = 0; h < 2; ++h)
#pragma unroll
        for (int nt = 0; nt < 8; ++nt) {
            int col = nt * 8 + tig * 2;
            int r1 = w * 32 + h * 16 + gid, r2 = r1 + 8;
            if (r1 < nrows)
                *(float2 *)(g_hsp + (base + r1) * HID + col) = make_float2(c[h][nt][0], c[h][nt][1]);
            if (r2 < nrows)
                *(float2 *)(g_hsp + (base + r2) * HID + col) = make_float2(c[h][nt][2], c[h][nt][3]);
        }
}

// ---------------- GRU cell for one level ----------------
__global__ void k_gru(const float *__restrict__ Ur, const float *__restrict__ Uz,
                      const float *__restrict__ Uh, int lev) {
    __shared__ float hsS[4][HID];
    __shared__ float hrS[4][HID];
    const int segbase = g_segbase[lev];
    const int cnt = g_cnt[lev];
    if (blockIdx.x * 4 >= cnt) return;
    const int r = threadIdx.x >> 6;
    const int d = threadIdx.x & 63;
    const int ridx = blockIdx.x * 4 + r;
    const bool act = ridx < cnt;
    const size_t tt = (size_t)segbase + (act ? ridx : (cnt - 1));
    const int node = g_order[tt];
    float hsv = 0.f;
#pragma unroll
    for (int s = 0; s < SPLIT; ++s) hsv += g_hsp[((size_t)s * NN + tt) * HID + d];
    hsS[r][d] = hsv;
    __syncthreads();
    float rr = g_xr[(size_t)node * HID + d];
    float zz = g_xz[(size_t)node * HID + d];
#pragma unroll
    for (int e = 0; e < HID; ++e) {
        float he = hsS[r][e];
        rr += he * Ur[e * HID + d];
        zz += he * Uz[e * HID + d];
    }
    rr = 1.f / (1.f + expf(-rr));
    zz = 1.f / (1.f + expf(-zz));
    hrS[r][d] = hsv * rr;
    __syncthreads();
    float hh = g_xh[(size_t)node * HID + d];
#pragma unroll
    for (int e = 0; e < HID; ++e) hh += hrS[r][e] * Uh[e * HID + d];
    hh = tanhf(hh);
    if (act) g_h[(size_t)node * HID + d] = rnd_tf32((1.f - zz) * hsv + zz * hh);
}

// ---------------- root readout ----------------
__global__ void k_root1(const int *__restrict__ level) {
    __shared__ float p[4][HID];
    const int g = threadIdx.x >> 6;
    const int d = threadIdx.x & 63;
    const int base = blockIdx.x * 256;
    float s = 0.f;
    for (int i = base + g; i < base + 256; i += 4)
        if (level[i] == 0) s += g_h[(size_t)i * HID + d];
    p[g][d] = s;
    __syncthreads();
    if (g == 0) g_rootp[blockIdx.x * HID + d] = p[0][d] + p[1][d] + p[2][d] + p[3][d];
}

__global__ void k_root2(const float *__restrict__ dec_w, const float *__restrict__ dec_b,
                        float *__restrict__ out) {
    __shared__ float root[HID];
    const int d = threadIdx.x;
    float s = 0.f;
#pragma unroll
    for (int b = 0; b < 64; ++b) s += g_rootp[b * HID + d];
    root[d] = s;
    __syncthreads();
    if (d < NCLS) {
        float l = dec_b[d];
#pragma unroll
        for (int e = 0; e < HID; ++e) l += root[e] * dec_w[e * NCLS + d];
        out[d] = l;
    }
}

// ---------------- launcher ----------------
extern "C" void kernel_launch(void *const *d_in, const int *in_sizes, int n_in,
                              void *d_out, int out_size) {
    const float *adj   = (const float *)d_in[0];
    const float *tfidf = (const float *)d_in[1];
    const int   *level = (const int *)d_in[2];
    const float *E     = (const float *)d_in[3];
    const float *Wr    = (const float *)d_in[4];
    const float *Wz    = (const float *)d_in[5];
    const float *Ur    = (const float *)d_in[6];
    const float *Uz    = (const float *)d_in[7];
    const float *Wh    = (const float *)d_in[8];
    const float *Uh    = (const float *)d_in[9];
    const float *dec_w = (const float *)d_in[10];
    const float *dec_b = (const float *)d_in[11];
    float *out = (float *)d_out;

    cudaFuncSetAttribute(k_hs, cudaFuncAttributeMaxDynamicSharedMemorySize, SMEMSZ);
    cudaFuncSetAttribute(k_emb, cudaFuncAttributeMaxDynamicSharedMemorySize, SMEMSZ);

    k_zero<<<(NN * HID / 4) / 256, 256>>>();
    k_order<<<1, 1024>>>(level);
    k_emb<<<NN / 64, 128, SMEMSZ>>>(tfidf, E, Wr, Wz, Wh);
    for (int j = NLEV - 1; j >= 0; --j) {
        k_hs<<<dim3(MAXROWB, SPLIT), 128, SMEMSZ>>>(adj, j);
        k_gru<<<(MAXROWB * 128) / 4, 256>>>(Ur, Uz, Uh, j);
    }
    k_root1<<<64, 256>>>(level);
    k_root2<<<1, 64>>>(dec_w, dec_b, out);
}